// round 16
// baseline (speedup 1.0000x reference)
#include <cuda_runtime.h>
#include <cuda_fp16.h>
#include <cstdint>
#include <math.h>

#define EPSF 1e-5f

static const int N_TOK = 16384;   // B*T = 8*2048
static const int DIM   = 1024;
static const int FF    = 4096;

// ---------------- scratch (device globals; allocation-free) ----------------
__device__ __half   g_w1h[(size_t)FF * DIM];      // 8 MB  (quantized ints as half)
__device__ __half   g_w2h[(size_t)DIM * FF];      // 8 MB
__device__ __half   g_a1h[(size_t)N_TOK * DIM];   // 32 MB
__device__ __half   g_a2h[(size_t)N_TOK * FF];    // 128 MB
__device__ __half   g_h  [(size_t)N_TOK * FF];    // 128 MB (swish output, fp16)
__device__ float    g_dqa1[N_TOK];
__device__ unsigned g_hmax[N_TOK];                // float bits, idempotent max
__device__ unsigned g_wmax[2];                    // float bits
__device__ unsigned g_ctr2;                       // GEMM2 persistent tile counter

// ---------------- small PTX helpers ----------------
__device__ __forceinline__ void cp16(uint32_t dst, const void* src) {
    asm volatile("cp.async.cg.shared.global [%0], [%1], 16;\n" :: "r"(dst), "l"(src));
}
__device__ __forceinline__ void cp_commit() { asm volatile("cp.async.commit_group;\n"); }
template<int N> __device__ __forceinline__ void cp_wait() {
    asm volatile("cp.async.wait_group %0;\n" :: "n"(N));
}
__device__ __forceinline__ void ldsm4(uint32_t& r0, uint32_t& r1, uint32_t& r2, uint32_t& r3,
                                      uint32_t addr) {
    asm volatile("ldmatrix.sync.aligned.m8n8.x4.shared.b16 {%0,%1,%2,%3}, [%4];"
                 : "=r"(r0), "=r"(r1), "=r"(r2), "=r"(r3) : "r"(addr));
}
__device__ __forceinline__ void st_cs_f2(float* p, float a, float b) {
    asm volatile("st.global.cs.v2.f32 [%0], {%1, %2};" :: "l"(p), "f"(a), "f"(b) : "memory");
}
__device__ __forceinline__ void st_cs_u1(void* p, uint32_t a) {
    asm volatile("st.global.cs.u32 [%0], %1;" :: "l"(p), "r"(a) : "memory");
}
__device__ __forceinline__ uint4 ld_cs_u4(const uint4* p) {
    uint4 v;
    asm volatile("ld.global.cs.v4.u32 {%0,%1,%2,%3}, [%4];"
                 : "=r"(v.x), "=r"(v.y), "=r"(v.z), "=r"(v.w) : "l"(p));
    return v;
}
__device__ __forceinline__ void st_cs_u4(void* p, uint4 v) {
    asm volatile("st.global.cs.v4.u32 [%0], {%1,%2,%3,%4};"
                 :: "l"(p), "r"(v.x), "r"(v.y), "r"(v.z), "r"(v.w) : "memory");
}
#define HMMA16816(acc, a0, a1, a2, a3, b0, b1) \
    asm volatile("mma.sync.aligned.m16n8k16.row.col.f32.f16.f16.f32 " \
                 "{%0,%1,%2,%3}, {%4,%5,%6,%7}, {%8,%9}, {%0,%1,%2,%3};\n" \
                 : "+f"((acc)[0]), "+f"((acc)[1]), "+f"((acc)[2]), "+f"((acc)[3]) \
                 : "r"(a0), "r"(a1), "r"(a2), "r"(a3), "r"(b0), "r"(b1))

// ======================= GEMM1 (R15 config, proven 357us) =======================
// BM=128, BN=128, BK=64. 256 threads = 8 warps 2(m) x 4(n), warp tile 64x32.
// 3-stage cp.async, 96KB, 2 CTAs/SM. Streaming fp16 h stores.
__launch_bounds__(256, 2)
__global__ void gemm1_f16_k(const float* __restrict__ bias) {
    constexpr int K  = DIM;
    constexpr int KT = K / 64;
    constexpr int STAGE = 128 * 128 * 2;             // 32KB

    const __half* __restrict__ A  = g_a1h;
    const __half* __restrict__ Bw = g_w1h;

    extern __shared__ int8_t sm[];

    const int tid  = threadIdx.x;
    const int lane = tid & 31;
    const int warp = tid >> 5;
    const int wm   = warp >> 2;
    const int wn   = warp & 3;
    const int bm   = blockIdx.y * 128;
    const int bn   = blockIdx.x * 128;

    float acc[4][4][4];
    #pragma unroll
    for (int mi = 0; mi < 4; mi++)
        #pragma unroll
        for (int ni = 0; ni < 4; ni++)
            #pragma unroll
            for (int j = 0; j < 4; j++) acc[mi][ni][j] = 0.f;

    auto ld_stage = [&](int stg, int kt) {
        uint32_t ab = (uint32_t)__cvta_generic_to_shared(sm + stg * STAGE);
        uint32_t bb = ab + 128 * 128;
        #pragma unroll
        for (int i = 0; i < 4; i++) {
            int c = tid + i * 256;
            int row = c >> 3, ch = c & 7;
            uint32_t dst = ab + row * 128 + ((ch ^ (row & 7)) << 4);
            cp16(dst, (const int8_t*)A + (size_t)(bm + row) * (K * 2) + kt * 128 + ch * 16);
        }
        #pragma unroll
        for (int i = 0; i < 4; i++) {
            int c = tid + i * 256;
            int row = c >> 3, ch = c & 7;
            uint32_t dst = bb + row * 128 + ((ch ^ (row & 7)) << 4);
            cp16(dst, (const int8_t*)Bw + (size_t)(bn + row) * (K * 2) + kt * 128 + ch * 16);
        }
        cp_commit();
    };

    ld_stage(0, 0);
    ld_stage(1, 1);

    for (int kt = 0; kt < KT; ++kt) {
        if (kt + 2 < KT) { cp_wait<1>(); } else { cp_wait<0>(); }
        __syncthreads();
        if (kt + 2 < KT) ld_stage((kt + 2) % 3, kt + 2);

        uint32_t abase = (uint32_t)__cvta_generic_to_shared(sm + (kt % 3) * STAGE);
        uint32_t bbase = abase + 128 * 128;

        #pragma unroll
        for (int ks = 0; ks < 4; ++ks) {
            uint32_t af[4][4], bf[4][2];
            #pragma unroll
            for (int mi = 0; mi < 4; mi++) {
                int row = wm * 64 + mi * 16 + (lane & 15);
                int ch  = 2 * ks + (lane >> 4);
                uint32_t a = abase + row * 128 + ((ch ^ (row & 7)) << 4);
                ldsm4(af[mi][0], af[mi][1], af[mi][2], af[mi][3], a);
            }
            #pragma unroll
            for (int p = 0; p < 2; p++) {
                int row = wn * 32 + p * 16 + ((lane >> 4) << 3) + (lane & 7);
                int ch  = 2 * ks + ((lane >> 3) & 1);
                uint32_t a = bbase + row * 128 + ((ch ^ (row & 7)) << 4);
                ldsm4(bf[2 * p][0], bf[2 * p][1], bf[2 * p + 1][0], bf[2 * p + 1][1], a);
            }
            #pragma unroll
            for (int mi = 0; mi < 4; mi++)
                #pragma unroll
                for (int ni = 0; ni < 4; ni++)
                    HMMA16816(acc[mi][ni], af[mi][0], af[mi][1], af[mi][2], af[mi][3],
                              bf[ni][0], bf[ni][1]);
        }
    }

    // epilogue: swish + streaming fp16 h store + row absmax
    const float dqw = fmaxf(__uint_as_float(g_wmax[0]), EPSF) * (1.f / 127.f);
    #pragma unroll
    for (int mi = 0; mi < 4; mi++) {
        #pragma unroll
        for (int half = 0; half < 2; ++half) {
            int row = bm + wm * 64 + mi * 16 + (lane >> 2) + half * 8;
            float f = g_dqa1[row] * dqw;
            float rmax = 0.f;
            #pragma unroll
            for (int ni = 0; ni < 4; ni++) {
                int col = bn + wn * 32 + ni * 8 + (lane & 3) * 2;
                float v0 = acc[mi][ni][half * 2 + 0] * f + __ldg(&bias[col]);
                float v1 = acc[mi][ni][half * 2 + 1] * f + __ldg(&bias[col + 1]);
                float h0 = v0 / (1.f + __expf(-v0));
                float h1 = v1 / (1.f + __expf(-v1));
                __half2 hh = __floats2half2_rn(h0, h1);
                st_cs_u1(&g_h[(size_t)row * FF + col], *(uint32_t*)&hh);
                rmax = fmaxf(rmax, fmaxf(fabsf(h0), fabsf(h1)));
            }
            rmax = fmaxf(rmax, __shfl_xor_sync(0xffffffffu, rmax, 1));
            rmax = fmaxf(rmax, __shfl_xor_sync(0xffffffffu, rmax, 2));
            if ((lane & 3) == 0) atomicMax(&g_hmax[row], __float_as_uint(rmax));
        }
    }
}

// ======================= GEMM2: persistent tile scheduler =======================
// Same R8 tile/mainloop (BM=128, BN=128, BK=64, 8 warps 2x4, 3 stages, 96KB,
// 2 CTAs/SM). 304 persistent CTAs pull tile ids 0..1023 from g_ctr2 (reset by
// quant_h): removes the ragged 3.46-wave quantization with ZERO extra traffic.
// Counter order == old (bn fast, bm slow) -> same L2 A-panel sharing.
__launch_bounds__(256, 2)
__global__ void gemm2_f16_k(const float* __restrict__ bias,
                            const float* __restrict__ xres,
                            const float* __restrict__ mask,
                            float* __restrict__ out) {
    constexpr int K  = FF;
    constexpr int KT = K / 64;                       // 64 slabs
    constexpr int STAGE = 128 * 128 * 2;             // 32KB
    constexpr unsigned NTILES = (DIM / 128) * (N_TOK / 128);   // 1024

    const __half* __restrict__ A  = g_a2h;
    const __half* __restrict__ Bw = g_w2h;

    extern __shared__ int8_t sm[];
    __shared__ unsigned s_tile;

    const int tid  = threadIdx.x;
    const int lane = tid & 31;
    const int warp = tid >> 5;
    const int wm   = warp >> 2;
    const int wn   = warp & 3;

    const float dqw = fmaxf(__uint_as_float(g_wmax[1]), EPSF) * (1.f / 127.f);

    for (;;) {
        if (tid == 0) s_tile = atomicAdd(&g_ctr2, 1u);
        __syncthreads();                 // broadcast tile id; also guards smem reuse
        const unsigned t = s_tile;
        if (t >= NTILES) return;
        const int bn = (int)(t & 7u) * 128;          // DIM/128 = 8, fast-varying
        const int bm = (int)(t >> 3) * 128;

        float acc[4][4][4];
        #pragma unroll
        for (int mi = 0; mi < 4; mi++)
            #pragma unroll
            for (int ni = 0; ni < 4; ni++)
                #pragma unroll
                for (int j = 0; j < 4; j++) acc[mi][ni][j] = 0.f;

        auto ld_stage = [&](int stg, int kt) {
            uint32_t ab = (uint32_t)__cvta_generic_to_shared(sm + stg * STAGE);
            uint32_t bb = ab + 128 * 128;
            #pragma unroll
            for (int i = 0; i < 4; i++) {
                int c = tid + i * 256;
                int row = c >> 3, ch = c & 7;
                uint32_t dst = ab + row * 128 + ((ch ^ (row & 7)) << 4);
                cp16(dst, (const int8_t*)A + (size_t)(bm + row) * (K * 2) + kt * 128 + ch * 16);
            }
            #pragma unroll
            for (int i = 0; i < 4; i++) {
                int c = tid + i * 256;
                int row = c >> 3, ch = c & 7;
                uint32_t dst = bb + row * 128 + ((ch ^ (row & 7)) << 4);
                cp16(dst, (const int8_t*)Bw + (size_t)(bn + row) * (K * 2) + kt * 128 + ch * 16);
            }
            cp_commit();
        };

        ld_stage(0, 0);
        ld_stage(1, 1);

        for (int kt = 0; kt < KT; ++kt) {
            if (kt + 2 < KT) { cp_wait<1>(); } else { cp_wait<0>(); }
            __syncthreads();
            if (kt + 2 < KT) ld_stage((kt + 2) % 3, kt + 2);

            uint32_t abase = (uint32_t)__cvta_generic_to_shared(sm + (kt % 3) * STAGE);
            uint32_t bbase = abase + 128 * 128;

            #pragma unroll
            for (int ks = 0; ks < 4; ++ks) {
                uint32_t af[4][4], bf[4][2];
                #pragma unroll
                for (int mi = 0; mi < 4; mi++) {
                    int row = wm * 64 + mi * 16 + (lane & 15);
                    int ch  = 2 * ks + (lane >> 4);
                    uint32_t a = abase + row * 128 + ((ch ^ (row & 7)) << 4);
                    ldsm4(af[mi][0], af[mi][1], af[mi][2], af[mi][3], a);
                }
                #pragma unroll
                for (int p = 0; p < 2; p++) {
                    int row = wn * 32 + p * 16 + ((lane >> 4) << 3) + (lane & 7);
                    int ch  = 2 * ks + ((lane >> 3) & 1);
                    uint32_t a = bbase + row * 128 + ((ch ^ (row & 7)) << 4);
                    ldsm4(bf[2 * p][0], bf[2 * p][1], bf[2 * p + 1][0], bf[2 * p + 1][1], a);
                }
                #pragma unroll
                for (int mi = 0; mi < 4; mi++)
                    #pragma unroll
                    for (int ni = 0; ni < 4; ni++)
                        HMMA16816(acc[mi][ni], af[mi][0], af[mi][1], af[mi][2], af[mi][3],
                                  bf[ni][0], bf[ni][1]);
            }
        }

        // epilogue: dequant + bias + mask + residual
        #pragma unroll
        for (int mi = 0; mi < 4; mi++) {
            #pragma unroll
            for (int half = 0; half < 2; ++half) {
                int row = bm + wm * 64 + mi * 16 + (lane >> 2) + half * 8;
                float f  = fmaxf(__uint_as_float(g_hmax[row]), EPSF) * (1.f / 127.f) * dqw;
                float mk = mask[row];
                #pragma unroll
                for (int ni = 0; ni < 4; ni++) {
                    int col = bn + wn * 32 + ni * 8 + (lane & 3) * 2;
                    float v0 = acc[mi][ni][half * 2 + 0] * f + __ldg(&bias[col]);
                    float v1 = acc[mi][ni][half * 2 + 1] * f + __ldg(&bias[col + 1]);
                    const float2 xv = *(const float2*)&xres[(size_t)row * DIM + col];
                    st_cs_f2(&out[(size_t)row * DIM + col],
                             xv.x + 0.5f * v0 * mk, xv.y + 0.5f * v1 * mk);
                }
            }
        }
    }
}

// ======================= elementwise kernels =======================
__global__ void absmax_both_k(const float4* __restrict__ w1,
                              const float4* __restrict__ w2, int n4) {
    const int wi = blockIdx.y;
    const float4* __restrict__ x = wi ? w2 : w1;
    float m = 0.f;
    for (int i = blockIdx.x * blockDim.x + threadIdx.x; i < n4; i += gridDim.x * blockDim.x) {
        float4 v = x[i];
        m = fmaxf(m, fmaxf(fmaxf(fabsf(v.x), fabsf(v.y)), fmaxf(fabsf(v.z), fabsf(v.w))));
    }
    #pragma unroll
    for (int o = 16; o; o >>= 1) m = fmaxf(m, __shfl_xor_sync(0xffffffffu, m, o));
    __shared__ float sh[32];
    if ((threadIdx.x & 31) == 0) sh[threadIdx.x >> 5] = m;
    __syncthreads();
    if (threadIdx.x < 32) {
        m = (threadIdx.x < (blockDim.x >> 5)) ? sh[threadIdx.x] : 0.f;
        #pragma unroll
        for (int o = 16; o; o >>= 1) m = fmaxf(m, __shfl_xor_sync(0xffffffffu, m, o));
        if (threadIdx.x == 0) atomicMax(&g_wmax[wi], __float_as_uint(m));
    }
}

__global__ void quantw_both_k(const float4* __restrict__ w1,
                              const float4* __restrict__ w2, int n4) {
    const int wi = blockIdx.y;
    const float4* __restrict__ w = wi ? w2 : w1;
    int i = blockIdx.x * blockDim.x + threadIdx.x;
    if (i >= n4) return;
    float s = 127.f / fmaxf(__uint_as_float(g_wmax[wi]), EPSF);
    float4 v = w[i];
    __half2 h0 = __floats2half2_rn(rintf(fminf(fmaxf(v.x * s, -127.f), 127.f)),
                                   rintf(fminf(fmaxf(v.y * s, -127.f), 127.f)));
    __half2 h1 = __floats2half2_rn(rintf(fminf(fmaxf(v.z * s, -127.f), 127.f)),
                                   rintf(fminf(fmaxf(v.w * s, -127.f), 127.f)));
    __half2* dst = (__half2*)(wi ? g_w2h : g_w1h);
    dst[2 * i]     = h0;
    dst[2 * i + 1] = h1;
}

__global__ void ln_quant_k(const float4* __restrict__ x,
                           const float4* __restrict__ gamma,
                           const float4* __restrict__ beta) {
    const int row = blockIdx.x;
    const int t   = threadIdx.x;           // 256 threads, D/4 = 256 float4
    __shared__ float sh[8];

    float4 v = x[(size_t)row * 256 + t];
    float s = v.x + v.y + v.z + v.w;
    #pragma unroll
    for (int o = 16; o; o >>= 1) s += __shfl_xor_sync(0xffffffffu, s, o);
    if ((t & 31) == 0) sh[t >> 5] = s;
    __syncthreads();
    float mu = sh[0];
    #pragma unroll
    for (int i = 1; i < 8; i++) mu += sh[i];
    mu *= (1.f / 1024.f);
    __syncthreads();

    float d0 = v.x - mu, d1 = v.y - mu, d2 = v.z - mu, d3 = v.w - mu;
    float ss = d0*d0 + d1*d1 + d2*d2 + d3*d3;
    #pragma unroll
    for (int o = 16; o; o >>= 1) ss += __shfl_xor_sync(0xffffffffu, ss, o);
    if ((t & 31) == 0) sh[t >> 5] = ss;
    __syncthreads();
    float var = sh[0];
    #pragma unroll
    for (int i = 1; i < 8; i++) var += sh[i];
    var *= (1.f / 1024.f);
    __syncthreads();

    float rstd = rsqrtf(var + EPSF);
    float4 g = gamma[t], b = beta[t];
    float y0 = d0 * rstd * g.x + b.x;
    float y1 = d1 * rstd * g.y + b.y;
    float y2 = d2 * rstd * g.z + b.z;
    float y3 = d3 * rstd * g.w + b.w;

    float am = fmaxf(fmaxf(fabsf(y0), fabsf(y1)), fmaxf(fabsf(y2), fabsf(y3)));
    #pragma unroll
    for (int o = 16; o; o >>= 1) am = fmaxf(am, __shfl_xor_sync(0xffffffffu, am, o));
    if ((t & 31) == 0) sh[t >> 5] = am;
    __syncthreads();
    float amax = sh[0];
    #pragma unroll
    for (int i = 1; i < 8; i++) amax = fmaxf(amax, sh[i]);

    amax = fmaxf(amax, EPSF);
    float sc = 127.f / amax;
    __half2 h0 = __floats2half2_rn(rintf(fminf(fmaxf(y0 * sc, -127.f), 127.f)),
                                   rintf(fminf(fmaxf(y1 * sc, -127.f), 127.f)));
    __half2 h1 = __floats2half2_rn(rintf(fminf(fmaxf(y2 * sc, -127.f), 127.f)),
                                   rintf(fminf(fmaxf(y3 * sc, -127.f), 127.f)));
    __half2* dst = (__half2*)g_a1h;
    dst[(size_t)row * 512 + 2 * t]     = h0;
    dst[(size_t)row * 512 + 2 * t + 1] = h1;
    if (t == 0) g_dqa1[row] = amax * (1.f / 127.f);
}

// Pure 256MB fp16 stream: 8 halves (16B) per thread, .cs both sides.
// Also resets the GEMM2 persistent tile counter (runs right before GEMM2).
__global__ void quant_h_k() {
    if (blockIdx.x == 0 && threadIdx.x == 0) g_ctr2 = 0u;
    size_t idx = (size_t)blockIdx.x * blockDim.x + threadIdx.x;  // one uint4 = 8 halves
    int row = (int)(idx >> 9);                       // FF/8 = 512 uint4 per row
    float s = 127.f / fmaxf(__uint_as_float(g_hmax[row]), EPSF);
    uint4 v = ld_cs_u4((const uint4*)g_h + idx);
    uint4 o;
    uint32_t* vi = (uint32_t*)&v;
    uint32_t* oi = (uint32_t*)&o;
    #pragma unroll
    for (int w = 0; w < 4; w++) {
        __half2 p = *(__half2*)&vi[w];
        float lo = __low2float(p), hi = __high2float(p);
        __half2 q = __floats2half2_rn(
            rintf(fminf(fmaxf(lo * s, -127.f), 127.f)),
            rintf(fminf(fmaxf(hi * s, -127.f), 127.f)));
        oi[w] = *(uint32_t*)&q;
    }
    st_cs_u4((uint4*)g_a2h + idx, o);
}

// ======================= launcher =======================
extern "C" void kernel_launch(void* const* d_in, const int* in_sizes, int n_in,
                              void* d_out, int out_size) {
    const float* x     = (const float*)d_in[0];
    const float* mask  = (const float*)d_in[1];
    const float* gamma = (const float*)d_in[2];
    const float* beta  = (const float*)d_in[3];
    const float* w1    = (const float*)d_in[4];
    const float* b1    = (const float*)d_in[5];
    const float* w2    = (const float*)d_in[6];
    const float* b2    = (const float*)d_in[7];
    float* out = (float*)d_out;

    const int wn4 = (FF * DIM) / 4;
    const int GEMM_SMEM = 3 * 128 * 128 * 2;       // 96KB
    cudaFuncSetAttribute(gemm1_f16_k, cudaFuncAttributeMaxDynamicSharedMemorySize, GEMM_SMEM);
    cudaFuncSetAttribute(gemm2_f16_k, cudaFuncAttributeMaxDynamicSharedMemorySize, GEMM_SMEM);

    // weights: absmax -> quantize to fp16 ints (idempotent across graph replays)
    absmax_both_k<<<dim3(1024, 2), 256>>>((const float4*)w1, (const float4*)w2, wn4);
    quantw_both_k<<<dim3(wn4 / 256, 2), 256>>>((const float4*)w1, (const float4*)w2, wn4);

    // LN + per-token act quant -> fp16 ints
    ln_quant_k<<<N_TOK, 256>>>((const float4*)x, (const float4*)gamma, (const float4*)beta);

    // GEMM1 + swish + row absmax (streaming fp16 h stores)
    gemm1_f16_k<<<dim3(FF / 128, N_TOK / 128), 256, GEMM_SMEM>>>(b1);

    // quantize h -> fp16 ints; resets GEMM2 tile counter
    quant_h_k<<<(N_TOK * (FF / 8)) / 256, 256>>>();

    // GEMM2 + residual: 304 persistent CTAs (2/SM) pull 1024 tiles
    gemm2_f16_k<<<304, 256, GEMM_SMEM>>>(b2, x, mask, out);
}

// round 17
// speedup vs baseline: 1.1162x; 1.1162x over previous
#include <cuda_runtime.h>
#include <cuda_fp16.h>
#include <cstdint>
#include <math.h>

#define EPSF 1e-5f

static const int N_TOK = 16384;   // B*T = 8*2048
static const int DIM   = 1024;
static const int FF    = 4096;

// ---------------- scratch (device globals; allocation-free) ----------------
__device__ __half   g_w1h[(size_t)FF * DIM];      // 8 MB  (quantized ints as half)
__device__ __half   g_w2h[(size_t)DIM * FF];      // 8 MB
__device__ __half   g_a1h[(size_t)N_TOK * DIM];   // 32 MB
__device__ __half   g_a2h[(size_t)N_TOK * FF];    // 128 MB
__device__ __half   g_h  [(size_t)N_TOK * FF];    // 128 MB (swish output, fp16)
__device__ float    g_dqa1[N_TOK];
__device__ unsigned g_hmax[N_TOK];                // float bits, idempotent max
__device__ unsigned g_wmax[2];                    // float bits

// ---------------- small PTX helpers ----------------
__device__ __forceinline__ void cp16(uint32_t dst, const void* src) {
    asm volatile("cp.async.cg.shared.global [%0], [%1], 16;\n" :: "r"(dst), "l"(src));
}
__device__ __forceinline__ void cp_commit() { asm volatile("cp.async.commit_group;\n"); }
template<int N> __device__ __forceinline__ void cp_wait() {
    asm volatile("cp.async.wait_group %0;\n" :: "n"(N));
}
__device__ __forceinline__ void ldsm4(uint32_t& r0, uint32_t& r1, uint32_t& r2, uint32_t& r3,
                                      uint32_t addr) {
    asm volatile("ldmatrix.sync.aligned.m8n8.x4.shared.b16 {%0,%1,%2,%3}, [%4];"
                 : "=r"(r0), "=r"(r1), "=r"(r2), "=r"(r3) : "r"(addr));
}
__device__ __forceinline__ void st_cs_f2(float* p, float a, float b) {
    asm volatile("st.global.cs.v2.f32 [%0], {%1, %2};" :: "l"(p), "f"(a), "f"(b) : "memory");
}
__device__ __forceinline__ void st_cs_u1(void* p, uint32_t a) {
    asm volatile("st.global.cs.u32 [%0], %1;" :: "l"(p), "r"(a) : "memory");
}
__device__ __forceinline__ uint4 ld_cs_u4(const uint4* p) {
    uint4 v;
    asm volatile("ld.global.cs.v4.u32 {%0,%1,%2,%3}, [%4];"
                 : "=r"(v.x), "=r"(v.y), "=r"(v.z), "=r"(v.w) : "l"(p));
    return v;
}
__device__ __forceinline__ void st_cs_u4(void* p, uint4 v) {
    asm volatile("st.global.cs.v4.u32 [%0], {%1,%2,%3,%4};"
                 :: "l"(p), "r"(v.x), "r"(v.y), "r"(v.z), "r"(v.w) : "memory");
}
#define HMMA16816(acc, a0, a1, a2, a3, b0, b1) \
    asm volatile("mma.sync.aligned.m16n8k16.row.col.f32.f16.f16.f32 " \
                 "{%0,%1,%2,%3}, {%4,%5,%6,%7}, {%8,%9}, {%0,%1,%2,%3};\n" \
                 : "+f"((acc)[0]), "+f"((acc)[1]), "+f"((acc)[2]), "+f"((acc)[3]) \
                 : "r"(a0), "r"(a1), "r"(a2), "r"(a3), "r"(b0), "r"(b1))

// ======================= fp16 GEMM via mma.sync m16n8k16 (R15 config) ==========
// BM=128, BN=128, BK=64 (128B rows). 256 threads = 8 warps as 2(m) x 4(n),
// warp tile 64x32. 3-stage cp.async pipeline, 96KB smem/CTA, 2 CTAs/SM.
// Smem swizzle: 16B chunk' = chunk ^ (row & 7).
//
// EPI==1: g_h = fp16(swish(dq(a1 @ w1^T) + b1)) [streaming stores], rowmax->g_hmax
// EPI==2: out = x + 0.5*mask*(dq(a2 @ w2^T) + b2)
template<int EPI>
__launch_bounds__(256, 2)
__global__ void gemm_f16_k(const float* __restrict__ bias,
                           const float* __restrict__ xres,
                           const float* __restrict__ mask,
                           float* __restrict__ out) {
    constexpr int K  = (EPI == 1) ? DIM : FF;        // elements (halves)
    constexpr int KT = K / 64;                       // BK=64 slabs
    constexpr int STAGE = 128 * 128 * 2;             // A 16KB + B 16KB = 32KB

    const __half* __restrict__ A  = (EPI == 1) ? g_a1h : g_a2h;
    const __half* __restrict__ Bw = (EPI == 1) ? g_w1h : g_w2h;

    extern __shared__ int8_t sm[];                   // 3 * 32KB

    const int tid  = threadIdx.x;
    const int lane = tid & 31;
    const int warp = tid >> 5;
    const int wm   = warp >> 2;                      // 0..1
    const int wn   = warp & 3;                       // 0..3
    const int bm   = blockIdx.y * 128;
    const int bn   = blockIdx.x * 128;

    float acc[4][4][4];
    #pragma unroll
    for (int mi = 0; mi < 4; mi++)
        #pragma unroll
        for (int ni = 0; ni < 4; ni++)
            #pragma unroll
            for (int j = 0; j < 4; j++) acc[mi][ni][j] = 0.f;

    auto ld_stage = [&](int stg, int kt) {
        uint32_t ab = (uint32_t)__cvta_generic_to_shared(sm + stg * STAGE);
        uint32_t bb = ab + 128 * 128;
        #pragma unroll
        for (int i = 0; i < 4; i++) {                // A: 1024 chunks of 16B
            int c = tid + i * 256;
            int row = c >> 3, ch = c & 7;
            uint32_t dst = ab + row * 128 + ((ch ^ (row & 7)) << 4);
            cp16(dst, (const int8_t*)A + (size_t)(bm + row) * (K * 2) + kt * 128 + ch * 16);
        }
        #pragma unroll
        for (int i = 0; i < 4; i++) {                // B: 1024 chunks of 16B
            int c = tid + i * 256;
            int row = c >> 3, ch = c & 7;
            uint32_t dst = bb + row * 128 + ((ch ^ (row & 7)) << 4);
            cp16(dst, (const int8_t*)Bw + (size_t)(bn + row) * (K * 2) + kt * 128 + ch * 16);
        }
        cp_commit();
    };

    ld_stage(0, 0);
    ld_stage(1, 1);

    for (int kt = 0; kt < KT; ++kt) {
        if (kt + 2 < KT) { cp_wait<1>(); } else { cp_wait<0>(); }
        __syncthreads();
        if (kt + 2 < KT) ld_stage((kt + 2) % 3, kt + 2);

        uint32_t abase = (uint32_t)__cvta_generic_to_shared(sm + (kt % 3) * STAGE);
        uint32_t bbase = abase + 128 * 128;

        #pragma unroll
        for (int ks = 0; ks < 4; ++ks) {             // four k16 steps per slab
            uint32_t af[4][4], bf[4][2];
            #pragma unroll
            for (int mi = 0; mi < 4; mi++) {
                int row = wm * 64 + mi * 16 + (lane & 15);
                int ch  = 2 * ks + (lane >> 4);
                uint32_t a = abase + row * 128 + ((ch ^ (row & 7)) << 4);
                ldsm4(af[mi][0], af[mi][1], af[mi][2], af[mi][3], a);
            }
            #pragma unroll
            for (int p = 0; p < 2; p++) {
                int row = wn * 32 + p * 16 + ((lane >> 4) << 3) + (lane & 7);
                int ch  = 2 * ks + ((lane >> 3) & 1);
                uint32_t a = bbase + row * 128 + ((ch ^ (row & 7)) << 4);
                ldsm4(bf[2 * p][0], bf[2 * p][1], bf[2 * p + 1][0], bf[2 * p + 1][1], a);
            }
            #pragma unroll
            for (int mi = 0; mi < 4; mi++)
                #pragma unroll
                for (int ni = 0; ni < 4; ni++)
                    HMMA16816(acc[mi][ni], af[mi][0], af[mi][1], af[mi][2], af[mi][3],
                              bf[ni][0], bf[ni][1]);
        }
    }

    // ---------------- epilogue ----------------
    const float dqw = fmaxf(__uint_as_float(g_wmax[EPI - 1]), EPSF) * (1.f / 127.f);

    if (EPI == 1) {
        #pragma unroll
        for (int mi = 0; mi < 4; mi++) {
            #pragma unroll
            for (int half = 0; half < 2; ++half) {
                int row = bm + wm * 64 + mi * 16 + (lane >> 2) + half * 8;
                float f = g_dqa1[row] * dqw;
                float rmax = 0.f;
                #pragma unroll
                for (int ni = 0; ni < 4; ni++) {
                    int col = bn + wn * 32 + ni * 8 + (lane & 3) * 2;
                    float v0 = acc[mi][ni][half * 2 + 0] * f + __ldg(&bias[col]);
                    float v1 = acc[mi][ni][half * 2 + 1] * f + __ldg(&bias[col + 1]);
                    float h0 = v0 / (1.f + __expf(-v0));       // v * sigmoid(v)
                    float h1 = v1 / (1.f + __expf(-v1));
                    __half2 hh = __floats2half2_rn(h0, h1);    // fp16 h (128MB stream)
                    st_cs_u1(&g_h[(size_t)row * FF + col], *(uint32_t*)&hh);
                    rmax = fmaxf(rmax, fmaxf(fabsf(h0), fabsf(h1)));
                }
                rmax = fmaxf(rmax, __shfl_xor_sync(0xffffffffu, rmax, 1));
                rmax = fmaxf(rmax, __shfl_xor_sync(0xffffffffu, rmax, 2));
                if ((lane & 3) == 0) atomicMax(&g_hmax[row], __float_as_uint(rmax));
            }
        }
    } else {
        #pragma unroll
        for (int mi = 0; mi < 4; mi++) {
            #pragma unroll
            for (int half = 0; half < 2; ++half) {
                int row = bm + wm * 64 + mi * 16 + (lane >> 2) + half * 8;
                float f  = fmaxf(__uint_as_float(g_hmax[row]), EPSF) * (1.f / 127.f) * dqw;
                float mk = mask[row];
                #pragma unroll
                for (int ni = 0; ni < 4; ni++) {
                    int col = bn + wn * 32 + ni * 8 + (lane & 3) * 2;
                    float v0 = acc[mi][ni][half * 2 + 0] * f + __ldg(&bias[col]);
                    float v1 = acc[mi][ni][half * 2 + 1] * f + __ldg(&bias[col + 1]);
                    const float2 xv = *(const float2*)&xres[(size_t)row * DIM + col];
                    st_cs_f2(&out[(size_t)row * DIM + col],
                             xv.x + 0.5f * v0 * mk, xv.y + 0.5f * v1 * mk);
                }
            }
        }
    }
}

// ======================= fused prep: ln_quant (+ weight absmax) =======================
// blocks [0, N_TOK): LN + per-token act quant for row blockIdx.x.
// blocks [N_TOK, N_TOK+2048): grid-stride absmax over w1 (first 1024) / w2 (next 1024).
// The two workloads are independent; fusing overlaps them and removes a launch gap.
__global__ void prep_k(const float4* __restrict__ x,
                       const float4* __restrict__ gamma,
                       const float4* __restrict__ beta,
                       const float4* __restrict__ w1,
                       const float4* __restrict__ w2, int wn4) {
    const int t = threadIdx.x;

    if (blockIdx.x >= N_TOK) {
        // ---- weight absmax part ----
        int b  = blockIdx.x - N_TOK;                 // 0..2047
        int wi = b >> 10;                            // 0: w1, 1: w2
        int bb = b & 1023;
        const float4* __restrict__ w = wi ? w2 : w1;
        float m = 0.f;
        for (int i = bb * blockDim.x + t; i < wn4; i += 1024 * blockDim.x) {
            float4 v = w[i];
            m = fmaxf(m, fmaxf(fmaxf(fabsf(v.x), fabsf(v.y)), fmaxf(fabsf(v.z), fabsf(v.w))));
        }
        #pragma unroll
        for (int o = 16; o; o >>= 1) m = fmaxf(m, __shfl_xor_sync(0xffffffffu, m, o));
        __shared__ float shm[8];
        if ((t & 31) == 0) shm[t >> 5] = m;
        __syncthreads();
        if (t < 32) {
            m = (t < (int)(blockDim.x >> 5)) ? shm[t] : 0.f;
            #pragma unroll
            for (int o = 16; o; o >>= 1) m = fmaxf(m, __shfl_xor_sync(0xffffffffu, m, o));
            if (t == 0) atomicMax(&g_wmax[wi], __float_as_uint(m));
        }
        return;
    }

    // ---- LN + act quant part ----
    const int row = blockIdx.x;
    __shared__ float sh[8];

    float4 v = x[(size_t)row * 256 + t];
    float s = v.x + v.y + v.z + v.w;
    #pragma unroll
    for (int o = 16; o; o >>= 1) s += __shfl_xor_sync(0xffffffffu, s, o);
    if ((t & 31) == 0) sh[t >> 5] = s;
    __syncthreads();
    float mu = sh[0];
    #pragma unroll
    for (int i = 1; i < 8; i++) mu += sh[i];
    mu *= (1.f / 1024.f);
    __syncthreads();

    float d0 = v.x - mu, d1 = v.y - mu, d2 = v.z - mu, d3 = v.w - mu;
    float ss = d0*d0 + d1*d1 + d2*d2 + d3*d3;
    #pragma unroll
    for (int o = 16; o; o >>= 1) ss += __shfl_xor_sync(0xffffffffu, ss, o);
    if ((t & 31) == 0) sh[t >> 5] = ss;
    __syncthreads();
    float var = sh[0];
    #pragma unroll
    for (int i = 1; i < 8; i++) var += sh[i];
    var *= (1.f / 1024.f);
    __syncthreads();

    float rstd = rsqrtf(var + EPSF);
    float4 g = gamma[t], b = beta[t];
    float y0 = d0 * rstd * g.x + b.x;
    float y1 = d1 * rstd * g.y + b.y;
    float y2 = d2 * rstd * g.z + b.z;
    float y3 = d3 * rstd * g.w + b.w;

    float am = fmaxf(fmaxf(fabsf(y0), fabsf(y1)), fmaxf(fabsf(y2), fabsf(y3)));
    #pragma unroll
    for (int o = 16; o; o >>= 1) am = fmaxf(am, __shfl_xor_sync(0xffffffffu, am, o));
    if ((t & 31) == 0) sh[t >> 5] = am;
    __syncthreads();
    float amax = sh[0];
    #pragma unroll
    for (int i = 1; i < 8; i++) amax = fmaxf(amax, sh[i]);

    amax = fmaxf(amax, EPSF);
    float sc = 127.f / amax;
    __half2 h0 = __floats2half2_rn(rintf(fminf(fmaxf(y0 * sc, -127.f), 127.f)),
                                   rintf(fminf(fmaxf(y1 * sc, -127.f), 127.f)));
    __half2 h1 = __floats2half2_rn(rintf(fminf(fmaxf(y2 * sc, -127.f), 127.f)),
                                   rintf(fminf(fmaxf(y3 * sc, -127.f), 127.f)));
    __half2* dst = (__half2*)g_a1h;
    dst[(size_t)row * 512 + 2 * t]     = h0;
    dst[(size_t)row * 512 + 2 * t + 1] = h1;
    if (t == 0) g_dqa1[row] = amax * (1.f / 127.f);
}

__global__ void quantw_both_k(const float4* __restrict__ w1,
                              const float4* __restrict__ w2, int n4) {
    const int wi = blockIdx.y;
    const float4* __restrict__ w = wi ? w2 : w1;
    int i = blockIdx.x * blockDim.x + threadIdx.x;
    if (i >= n4) return;
    float s = 127.f / fmaxf(__uint_as_float(g_wmax[wi]), EPSF);
    float4 v = w[i];
    __half2 h0 = __floats2half2_rn(rintf(fminf(fmaxf(v.x * s, -127.f), 127.f)),
                                   rintf(fminf(fmaxf(v.y * s, -127.f), 127.f)));
    __half2 h1 = __floats2half2_rn(rintf(fminf(fmaxf(v.z * s, -127.f), 127.f)),
                                   rintf(fminf(fmaxf(v.w * s, -127.f), 127.f)));
    __half2* dst = (__half2*)(wi ? g_w2h : g_w1h);
    dst[2 * i]     = h0;
    dst[2 * i + 1] = h1;
}

// Pure 256MB fp16 stream: 8 halves (16B) per thread, .cs both sides.
__global__ void quant_h_k() {
    size_t idx = (size_t)blockIdx.x * blockDim.x + threadIdx.x;  // one uint4 = 8 halves
    int row = (int)(idx >> 9);                       // FF/8 = 512 uint4 per row
    float s = 127.f / fmaxf(__uint_as_float(g_hmax[row]), EPSF);
    uint4 v = ld_cs_u4((const uint4*)g_h + idx);
    uint4 o;
    uint32_t* vi = (uint32_t*)&v;
    uint32_t* oi = (uint32_t*)&o;
    #pragma unroll
    for (int w = 0; w < 4; w++) {
        __half2 p = *(__half2*)&vi[w];
        float lo = __low2float(p), hi = __high2float(p);
        __half2 q = __floats2half2_rn(
            rintf(fminf(fmaxf(lo * s, -127.f), 127.f)),
            rintf(fminf(fmaxf(hi * s, -127.f), 127.f)));
        oi[w] = *(uint32_t*)&q;
    }
    st_cs_u4((uint4*)g_a2h + idx, o);
}

// ======================= launcher =======================
extern "C" void kernel_launch(void* const* d_in, const int* in_sizes, int n_in,
                              void* d_out, int out_size) {
    const float* x     = (const float*)d_in[0];
    const float* mask  = (const float*)d_in[1];
    const float* gamma = (const float*)d_in[2];
    const float* beta  = (const float*)d_in[3];
    const float* w1    = (const float*)d_in[4];
    const float* b1    = (const float*)d_in[5];
    const float* w2    = (const float*)d_in[6];
    const float* b2    = (const float*)d_in[7];
    float* out = (float*)d_out;

    const int wn4 = (FF * DIM) / 4;
    const int GEMM_SMEM = 3 * 128 * 128 * 2;       // 96KB
    cudaFuncSetAttribute(gemm_f16_k<1>, cudaFuncAttributeMaxDynamicSharedMemorySize, GEMM_SMEM);
    cudaFuncSetAttribute(gemm_f16_k<2>, cudaFuncAttributeMaxDynamicSharedMemorySize, GEMM_SMEM);

    // fused: LN + act-quant rows (16384 blocks) || weight absmax (2048 blocks)
    prep_k<<<N_TOK + 2048, 256>>>((const float4*)x, (const float4*)gamma, (const float4*)beta,
                                  (const float4*)w1, (const float4*)w2, wn4);

    // weight quantize (needs absmax)
    quantw_both_k<<<dim3(wn4 / 256, 2), 256>>>((const float4*)w1, (const float4*)w2, wn4);

    // GEMM1 + swish + row absmax (streaming fp16 h stores)
    gemm_f16_k<1><<<dim3(FF / 128, N_TOK / 128), 256, GEMM_SMEM>>>(b1, nullptr, nullptr, nullptr);

    // quantize h -> fp16 ints (8 halves/thread)
    quant_h_k<<<(N_TOK * (FF / 8)) / 256, 256>>>();

    // GEMM2 + residual (R15 plain form)
    gemm_f16_k<2><<<dim3(DIM / 128, N_TOK / 128), 256, GEMM_SMEM>>>(b2, x, mask, out);
}